// round 6
// baseline (speedup 1.0000x reference)
#include <cuda_runtime.h>

#define DIM 64
#define TPB 256
#define ROWS_PER_T 2
#define CODES_PER_G 8
#define ROWS_PER_B (TPB * ROWS_PER_T)

typedef unsigned long long u64;

__device__ float g_partials[8192];
__device__ int   g_counter = 0;

__device__ __forceinline__ void fma2(u64 &acc, u64 a, u64 b) {
    asm("fma.rn.f32x2 %0, %1, %2, %0;" : "+l"(acc) : "l"(a), "l"(b));
}
__device__ __forceinline__ float2 asf2(u64 v) {
    float2 r; asm("mov.b64 {%0, %1}, %2;" : "=f"(r.x), "=f"(r.y) : "l"(v)); return r;
}
__device__ __forceinline__ u64 packf2(float lo, float hi) {
    u64 r; asm("mov.b64 %0, {%1, %2};" : "=l"(r) : "f"(lo), "f"(hi)); return r;
}

__global__ __launch_bounds__(TPB, 1) void vq_fused(
    const float* __restrict__ x, const float* __restrict__ cb,
    float* __restrict__ out, int N, int K, int nblocks,
    long q_off, long idx_off, long loss_off, float lscale)
{
    __shared__ float sesq[512];
    __shared__ float red[TPB];
    int tid = threadIdx.x;

    // Per-block e_sq (codebook is L2/L1-resident; cheap). Replicates
    // jnp.sum(e*e, axis=1): elementwise fl(e*e), sequential fp32 adds.
    for (int k = tid; k < K; k += TPB) {
        const float* e = cb + (long)k * DIM;
        float s = 0.f;
#pragma unroll
        for (int d = 0; d < DIM; d++)
            s = __fadd_rn(s, __fmul_rn(e[d], e[d]));
        sesq[k] = s;
    }
    __syncthreads();

    long row0 = (long)blockIdx.x * ROWS_PER_B + tid;
    long row1 = row0 + TPB;
    bool v0 = row0 < N, v1 = row1 < N;

    // Two x rows in registers as packed f32x2; x_sq with sequential rounding.
    u64 xp0[DIM / 2], xp1[DIM / 2];
    float xsq0 = 0.f, xsq1 = 0.f;
#pragma unroll
    for (int i = 0; i < DIM / 4; i++) {
        float4 a = v0 ? *reinterpret_cast<const float4*>(x + row0 * DIM + i * 4)
                      : make_float4(0.f, 0.f, 0.f, 0.f);
        float4 b = v1 ? *reinterpret_cast<const float4*>(x + row1 * DIM + i * 4)
                      : make_float4(0.f, 0.f, 0.f, 0.f);
        xp0[2 * i] = packf2(a.x, a.y); xp0[2 * i + 1] = packf2(a.z, a.w);
        xp1[2 * i] = packf2(b.x, b.y); xp1[2 * i + 1] = packf2(b.z, b.w);
        xsq0 = __fadd_rn(xsq0, __fmul_rn(a.x, a.x));
        xsq0 = __fadd_rn(xsq0, __fmul_rn(a.y, a.y));
        xsq0 = __fadd_rn(xsq0, __fmul_rn(a.z, a.z));
        xsq0 = __fadd_rn(xsq0, __fmul_rn(a.w, a.w));
        xsq1 = __fadd_rn(xsq1, __fmul_rn(b.x, b.x));
        xsq1 = __fadd_rn(xsq1, __fmul_rn(b.y, b.y));
        xsq1 = __fadd_rn(xsq1, __fmul_rn(b.z, b.z));
        xsq1 = __fadd_rn(xsq1, __fmul_rn(b.w, b.w));
    }

    float best0 = 3.4e38f, best1 = 3.4e38f;
    int   bidx0 = 0,       bidx1 = 0;

#pragma unroll 1
    for (int k0 = 0; k0 < K; k0 += CODES_PER_G) {
        // Codes streamed from GLOBAL (uniform address across warp -> one
        // L1-hit wavefront per LDG.128; LSU pipe, not the smem crossbar).
        const float* gbase = cb + (long)k0 * DIM;
        u64 acc0[CODES_PER_G], acc1[CODES_PER_G];
#pragma unroll
        for (int c = 0; c < CODES_PER_G; c++) { acc0[c] = 0ull; acc1[c] = 0ull; }

#pragma unroll
        for (int i = 0; i < DIM / 4; i++) {               // 16 chunks of 4 dims
#pragma unroll
            for (int c = 0; c < CODES_PER_G; c++) {       // const offsets off one base reg
                ulonglong2 e = *reinterpret_cast<const ulonglong2*>(gbase + c * DIM + i * 4);
                fma2(acc0[c], xp0[2 * i], e.x);
                fma2(acc0[c], xp0[2 * i + 1], e.y);
                fma2(acc1[c], xp1[2 * i], e.x);
                fma2(acc1[c], xp1[2 * i + 1], e.y);
            }
        }
        // Scores: fl(fl(x_sq + e_sq) - fl(2*dot)); first-occurrence argmin.
#pragma unroll
        for (int c = 0; c < CODES_PER_G; c++) {
            float eq = sesq[k0 + c];
            float2 f0 = asf2(acc0[c]);
            float d0 = f0.x + f0.y;
            float s0 = __fsub_rn(__fadd_rn(xsq0, eq), __fmul_rn(2.0f, d0));
            if (s0 < best0) { best0 = s0; bidx0 = k0 + c; }
            float2 f1 = asf2(acc1[c]);
            float d1 = f1.x + f1.y;
            float s1 = __fsub_rn(__fadd_rn(xsq1, eq), __fmul_rn(2.0f, d1));
            if (s1 < best1) { best1 = s1; bidx1 = k0 + c; }
        }
    }

    // Epilogue: winner code (L1/L2-hit); quantized_st = fl(x + fl(e - x)).
    float lsum = 0.f;
    bool q_vec = (q_off >= 0) && ((q_off & 3) == 0);
#pragma unroll 1
    for (int r = 0; r < ROWS_PER_T; r++) {
        long row  = r ? row1 : row0;
        int  bidx = r ? bidx1 : bidx0;
        u64* xp   = r ? xp1 : xp0;
        if (row >= N) break;
        const float4* eq = reinterpret_cast<const float4*>(cb + (long)bidx * DIM);
#pragma unroll
        for (int i = 0; i < DIM / 4; i++) {
            float4 e = eq[i];
            float2 lo = asf2(xp[2 * i]), hi = asf2(xp[2 * i + 1]);
            float d0 = __fsub_rn(e.x, lo.x), d1 = __fsub_rn(e.y, lo.y);
            float d2 = __fsub_rn(e.z, hi.x), d3 = __fsub_rn(e.w, hi.y);
            lsum += d0 * d0 + d1 * d1 + d2 * d2 + d3 * d3;
            if (q_off >= 0) {
                float* dst = out + q_off + row * DIM + i * 4;
                if (q_vec) {
                    float4 st = make_float4(__fadd_rn(lo.x, d0), __fadd_rn(lo.y, d1),
                                            __fadd_rn(hi.x, d2), __fadd_rn(hi.y, d3));
                    *reinterpret_cast<float4*>(dst) = st;
                } else {                                   // q_off==1: 4B-aligned only
                    dst[0] = __fadd_rn(lo.x, d0); dst[1] = __fadd_rn(lo.y, d1);
                    dst[2] = __fadd_rn(hi.x, d2); dst[3] = __fadd_rn(hi.y, d3);
                }
            }
        }
        if (idx_off >= 0) out[idx_off + row] = (float)bidx;
    }

    if (loss_off >= 0) {
        red[tid] = lsum;
        __syncthreads();
#pragma unroll
        for (int o = TPB / 2; o > 0; o >>= 1) {
            if (tid < o) red[tid] += red[tid + o];
            __syncthreads();
        }
        if (tid == 0) {
            g_partials[blockIdx.x] = red[0];
            __threadfence();
            int done = atomicAdd(&g_counter, 1);
            if (done == nblocks - 1) {                    // last block finishes the loss
                float s = 0.f;
                for (int i = 0; i < nblocks; i++) s += g_partials[i];  // fixed order
                out[loss_off] = s * lscale;
                g_counter = 0;                            // reset for next graph replay
            }
        }
    }
}

extern "C" void kernel_launch(void* const* d_in, const int* in_sizes, int n_in,
                              void* d_out, int out_size) {
    const float* a = (const float*)d_in[0];
    const float* b = (const float*)d_in[1];
    long s0 = in_sizes[0], s1 = in_sizes[1];
    const float *x, *cb; long xs, cs;
    if (s0 >= s1) { x = a; xs = s0; cb = b; cs = s1; }
    else          { x = b; xs = s1; cb = a; cs = s0; }

    int K = (int)(cs / DIM);
    int N = (int)(xs / DIM);
    long QN = (long)N * DIM;
    long osz = (long)out_size;

    // Output layout (confirmed R3/R4): [loss(1), quantized_st(QN), indices(N)]
    long loss_off = -1, q_off = -1, idx_off = -1;
    if      (osz == 1 + QN + N) { loss_off = 0; q_off = 1; idx_off = 1 + QN; }
    else if (osz == QN + N)     { q_off = 0; idx_off = QN; }
    else if (osz == QN)         { q_off = 0; }
    else if (osz == N)          { idx_off = 0; }
    else if (osz == 1)          { loss_off = 0; }
    else                        { loss_off = 0; q_off = 1; idx_off = 1 + QN; }

    float* out = (float*)d_out;
    int blocks = (N + ROWS_PER_B - 1) / ROWS_PER_B;
    float lscale = (float)(1.25 / ((double)N * (double)DIM));

    vq_fused<<<blocks, TPB>>>(x, cb, out, N, K, blocks,
                              q_off, idx_off, loss_off, lscale);
}